// round 5
// baseline (speedup 1.0000x reference)
#include <cuda_runtime.h>

#define ROWS_PER_BLOCK 16
#define TPB            512           // 16 warps = one warp per row
#define ROW_F          150           // floats per (b,t) row
#define N_BONES        50
#define EPS            1e-8f

// N = 128 * 1024 * 150
#define INV_N (1.0f / 19660800.0f)

__global__ __launch_bounds__(TPB)
void loss_kernel(const float* __restrict__ preds,
                 const float* __restrict__ targets,
                 float* __restrict__ out)
{
    __shared__ float pm[ROWS_PER_BLOCK * ROW_F];   // masked preds
    __shared__ float tm[ROWS_PER_BLOCK * ROW_F];   // targets (== masked targets)
    __shared__ float red[TPB / 32];

    const long long base = (long long)blockIdx.x * (ROWS_PER_BLOCK * ROW_F);
    // base*4 bytes = blockIdx * 9600 bytes -> 16B aligned; chunk = 600 float4s
    const float4* __restrict__ p4 = reinterpret_cast<const float4*>(preds + base);
    const float4* __restrict__ t4 = reinterpret_cast<const float4*>(targets + base);
    float4* pm4 = reinterpret_cast<float4*>(pm);
    float4* tm4 = reinterpret_cast<float4*>(tm);

    // ---- Phase 1: coalesced load + inline masked-L1 ----
    float l1 = 0.0f;
    #pragma unroll
    for (int i = threadIdx.x; i < (ROWS_PER_BLOCK * ROW_F) / 4; i += TPB) {
        float4 tv = t4[i];
        float4 pv = p4[i];
        float4 po;
        // mask m = (t != 0); t*m == t identically, p*m = (t!=0 ? p : 0)
        po.x = (tv.x != 0.0f) ? pv.x : 0.0f;
        po.y = (tv.y != 0.0f) ? pv.y : 0.0f;
        po.z = (tv.z != 0.0f) ? pv.z : 0.0f;
        po.w = (tv.w != 0.0f) ? pv.w : 0.0f;
        l1 += (tv.x != 0.0f) ? fabsf(pv.x - tv.x) : 0.0f;
        l1 += (tv.y != 0.0f) ? fabsf(pv.y - tv.y) : 0.0f;
        l1 += (tv.z != 0.0f) ? fabsf(pv.z - tv.z) : 0.0f;
        l1 += (tv.w != 0.0f) ? fabsf(pv.w - tv.w) : 0.0f;
        tm4[i] = tv;
        pm4[i] = po;
    }
    __syncthreads();

    // ---- Phase 2: bone directions, one warp per row ----
    const int warp = threadIdx.x >> 5;
    const int lane = threadIdx.x & 31;
    const float* __restrict__ pr = pm + warp * ROW_F;
    const float* __restrict__ tr = tm + warp * ROW_F;

    float mse = 0.0f;
    for (int k = lane; k < N_BONES; k += 32) {
        const int k1 = (k + 1 == N_BONES) ? 0 : (k + 1);
        const int s = 3 * k, d = 3 * k1;

        // preds (masked) bone diff
        float dp0 = pr[s + 0] - pr[d + 0];
        float dp1 = pr[s + 1] - pr[d + 1];
        float dp2 = pr[s + 2] - pr[d + 2];
        float invp = 1.0f / (sqrtf(dp0 * dp0 + dp1 * dp1 + dp2 * dp2) + EPS);

        // targets bone diff
        float t0 = tr[s + 0], t1 = tr[s + 1], t2 = tr[s + 2];
        float dt0 = t0 - tr[d + 0];
        float dt1 = t1 - tr[d + 1];
        float dt2 = t2 - tr[d + 2];
        float invt = 1.0f / (sqrtf(dt0 * dt0 + dt1 * dt1 + dt2 * dt2) + EPS);

        // direction-diff masked by (target[3k+c] != 0)
        float e0 = (t0 != 0.0f) ? (dp0 * invp - dt0 * invt) : 0.0f;
        float e1 = (t1 != 0.0f) ? (dp1 * invp - dt1 * invt) : 0.0f;
        float e2 = (t2 != 0.0f) ? (dp2 * invp - dt2 * invt) : 0.0f;
        mse += e0 * e0 + e1 * e1 + e2 * e2;
    }

    // ---- Phase 3: block reduce, one atomic per block ----
    float v = l1 + 0.1f * mse;
    #pragma unroll
    for (int o = 16; o > 0; o >>= 1)
        v += __shfl_xor_sync(0xffffffffu, v, o);
    if (lane == 0) red[warp] = v;
    __syncthreads();
    if (threadIdx.x < TPB / 32) {
        float s = red[threadIdx.x];
        #pragma unroll
        for (int o = 8; o > 0; o >>= 1)
            s += __shfl_xor_sync(0x0000ffffu, s, o, 16);
        if (threadIdx.x == 0)
            atomicAdd(out, s * INV_N);
    }
}

extern "C" void kernel_launch(void* const* d_in, const int* in_sizes, int n_in,
                              void* d_out, int out_size)
{
    const float* preds   = (const float*)d_in[0];
    const float* targets = (const float*)d_in[1];
    float* out = (float*)d_out;

    // d_out is poisoned to 0xAA — zero it (memset node is graph-capturable)
    cudaMemsetAsync(out, 0, sizeof(float));

    const int n_rows = in_sizes[0] / ROW_F;          // 131072
    const int blocks = n_rows / ROWS_PER_BLOCK;      // 8192 (divides exactly)
    loss_kernel<<<blocks, TPB>>>(preds, targets, out);
}

// round 6
// speedup vs baseline: 1.1794x; 1.1794x over previous
#include <cuda_runtime.h>

#define ROWS_PER_BLOCK 16
#define TPB            512           // 16 warps = one warp per row
#define ROW_F          150           // floats per (b,t) row

// N = 128 * 1024 * 150
#define INV_N (1.0f / 19660800.0f)

// Single-MUFU reciprocal sqrt (no IEEE refinement sequence).
__device__ __forceinline__ float rsqrt_fast(float x) {
    float y;
    asm("rsqrt.approx.f32 %0, %1;" : "=f"(y) : "f"(x));
    return y;
}

__global__ __launch_bounds__(TPB)
void loss_kernel(const float* __restrict__ preds,
                 const float* __restrict__ targets,
                 float* __restrict__ out)
{
    __shared__ float pm[ROWS_PER_BLOCK * ROW_F];   // masked preds
    __shared__ float tm[ROWS_PER_BLOCK * ROW_F];   // targets (== masked targets)
    __shared__ float red[TPB / 32];

    const long long base = (long long)blockIdx.x * (ROWS_PER_BLOCK * ROW_F);
    // base*4 bytes = blockIdx * 9600 bytes -> 16B aligned; chunk = 600 float4s
    const float4* __restrict__ p4 = reinterpret_cast<const float4*>(preds + base);
    const float4* __restrict__ t4 = reinterpret_cast<const float4*>(targets + base);
    float4* pm4 = reinterpret_cast<float4*>(pm);
    float4* tm4 = reinterpret_cast<float4*>(tm);

    // ---- Phase 1: coalesced load + inline masked-L1 ----
    float l1 = 0.0f;
    #pragma unroll
    for (int i = threadIdx.x; i < (ROWS_PER_BLOCK * ROW_F) / 4; i += TPB) {
        float4 tv = t4[i];
        float4 pv = p4[i];
        float4 po;
        // mask m = (t != 0); t*m == t identically, p*m = (t!=0 ? p : 0)
        po.x = (tv.x != 0.0f) ? pv.x : 0.0f;
        po.y = (tv.y != 0.0f) ? pv.y : 0.0f;
        po.z = (tv.z != 0.0f) ? pv.z : 0.0f;
        po.w = (tv.w != 0.0f) ? pv.w : 0.0f;
        l1 += (tv.x != 0.0f) ? fabsf(pv.x - tv.x) : 0.0f;
        l1 += (tv.y != 0.0f) ? fabsf(pv.y - tv.y) : 0.0f;
        l1 += (tv.z != 0.0f) ? fabsf(pv.z - tv.z) : 0.0f;
        l1 += (tv.w != 0.0f) ? fabsf(pv.w - tv.w) : 0.0f;
        tm4[i] = tv;
        pm4[i] = po;
    }
    __syncthreads();

    // ---- Phase 2: bone directions. One warp per row; lanes 0..24 each do
    //      two consecutive bones (2k, 2k+1), sharing the middle joint. ----
    const int warp = threadIdx.x >> 5;
    const int lane = threadIdx.x & 31;

    float mse = 0.0f;
    if (lane < 25) {
        const float* __restrict__ pr = pm + warp * ROW_F;
        const float* __restrict__ tr = tm + warp * ROW_F;

        const int s  = 6 * lane;                     // joint 2k base (floats)
        const int d2 = (lane == 24) ? 0 : (s + 6);   // joint (2k+2) % 50 base

        // three joints: a = 2k, b = 2k+1, c = (2k+2)%50
        float pax = pr[s + 0], pay = pr[s + 1], paz = pr[s + 2];
        float pbx = pr[s + 3], pby = pr[s + 4], pbz = pr[s + 5];
        float pcx = pr[d2 + 0], pcy = pr[d2 + 1], pcz = pr[d2 + 2];
        float tax = tr[s + 0], tay = tr[s + 1], taz = tr[s + 2];
        float tbx = tr[s + 3], tby = tr[s + 4], tbz = tr[s + 5];
        float tcx = tr[d2 + 0], tcy = tr[d2 + 1], tcz = tr[d2 + 2];

        // bone A: a -> b, direction mask = (t at joint a != 0)
        {
            float dx = pax - pbx, dy = pay - pby, dz = paz - pbz;
            float ip = rsqrt_fast(fmaf(dx, dx, fmaf(dy, dy, dz * dz)) + 1e-16f);
            float ex = tax - tbx, ey = tay - tby, ez = taz - tbz;
            float it = rsqrt_fast(fmaf(ex, ex, fmaf(ey, ey, ez * ez)) + 1e-16f);
            float gx = dx * ip - ex * it;
            float gy = dy * ip - ey * it;
            float gz = dz * ip - ez * it;
            mse += (tax != 0.0f) ? gx * gx : 0.0f;
            mse += (tay != 0.0f) ? gy * gy : 0.0f;
            mse += (taz != 0.0f) ? gz * gz : 0.0f;
        }
        // bone B: b -> c, direction mask = (t at joint b != 0)
        {
            float dx = pbx - pcx, dy = pby - pcy, dz = pbz - pcz;
            float ip = rsqrt_fast(fmaf(dx, dx, fmaf(dy, dy, dz * dz)) + 1e-16f);
            float ex = tbx - tcx, ey = tby - tcy, ez = tbz - tcz;
            float it = rsqrt_fast(fmaf(ex, ex, fmaf(ey, ey, ez * ez)) + 1e-16f);
            float gx = dx * ip - ex * it;
            float gy = dy * ip - ey * it;
            float gz = dz * ip - ez * it;
            mse += (tbx != 0.0f) ? gx * gx : 0.0f;
            mse += (tby != 0.0f) ? gy * gy : 0.0f;
            mse += (tbz != 0.0f) ? gz * gz : 0.0f;
        }
    }

    // ---- Phase 3: block reduce, one atomic per block ----
    float v = l1 + 0.1f * mse;
    #pragma unroll
    for (int o = 16; o > 0; o >>= 1)
        v += __shfl_xor_sync(0xffffffffu, v, o);
    if (lane == 0) red[warp] = v;
    __syncthreads();
    if (threadIdx.x < TPB / 32) {
        float s = red[threadIdx.x];
        #pragma unroll
        for (int o = 8; o > 0; o >>= 1)
            s += __shfl_xor_sync(0x0000ffffu, s, o, 16);
        if (threadIdx.x == 0)
            atomicAdd(out, s * INV_N);
    }
}

extern "C" void kernel_launch(void* const* d_in, const int* in_sizes, int n_in,
                              void* d_out, int out_size)
{
    const float* preds   = (const float*)d_in[0];
    const float* targets = (const float*)d_in[1];
    float* out = (float*)d_out;

    // d_out is poisoned to 0xAA — zero it (memset node is graph-capturable)
    cudaMemsetAsync(out, 0, sizeof(float));

    const int n_rows = in_sizes[0] / ROW_F;          // 131072
    const int blocks = n_rows / ROWS_PER_BLOCK;      // 8192 (divides exactly)
    loss_kernel<<<blocks, TPB>>>(preds, targets, out);
}